// round 1
// baseline (speedup 1.0000x reference)
#include <cuda_runtime.h>
#include <cstddef>

#define C_DIM 64
#define K_DIM 64
#define P_DIM (256 * 256)   // H*W = 65536

// Scratch accumulators (device globals — no allocation allowed).
__device__ float g_sums[K_DIM * C_DIM];
__device__ float g_counts[K_DIM];

// ---------------------------------------------------------------------------
// Kernel 0: zero the accumulators
// ---------------------------------------------------------------------------
__global__ void zero_kernel() {
    int tid = blockIdx.x * blockDim.x + threadIdx.x;
    for (int i = tid; i < K_DIM * C_DIM; i += gridDim.x * blockDim.x)
        g_sums[i] = 0.0f;
    if (tid < K_DIM) g_counts[tid] = 0.0f;
}

// ---------------------------------------------------------------------------
// Kernel 1: per-region sums and counts.
// Each block handles 256 pixels. Label recovered from one-hot by scan
// (coalesced: consecutive lanes read consecutive pixels for each k).
// Accumulate in padded smem tile, then one global atomic flush per block.
// ---------------------------------------------------------------------------
__global__ __launch_bounds__(256) void region_sums_kernel(
    const float* __restrict__ x, const float* __restrict__ oh)
{
    __shared__ float ssum[K_DIM][C_DIM + 1];  // pad to kill bank conflicts
    __shared__ float scnt[K_DIM];

    int tid = threadIdx.x;
    for (int i = tid; i < K_DIM * (C_DIM + 1); i += 256)
        (&ssum[0][0])[i] = 0.0f;
    if (tid < K_DIM) scnt[tid] = 0.0f;
    __syncthreads();

    int p = blockIdx.x * 256 + tid;

    // Find the one-hot label for this pixel.
    int label = 0;
    #pragma unroll 8
    for (int k = 0; k < K_DIM; k++) {
        if (__ldg(&oh[(size_t)k * P_DIM + p]) != 0.0f) label = k;
    }
    atomicAdd(&scnt[label], 1.0f);

    // Accumulate all channels of this pixel into the label's row.
    #pragma unroll 8
    for (int c = 0; c < C_DIM; c++) {
        atomicAdd(&ssum[label][c], __ldg(&x[(size_t)c * P_DIM + p]));
    }
    __syncthreads();

    // Flush block-partial sums to global (distinct addresses per thread-iter).
    for (int i = tid; i < K_DIM * C_DIM; i += 256) {
        int k = i >> 6, c = i & 63;
        float v = ssum[k][c];
        if (v != 0.0f) atomicAdd(&g_sums[i], v);
    }
    if (tid < K_DIM) {
        float v = scnt[tid];
        if (v != 0.0f) atomicAdd(&g_counts[tid], v);
    }
}

// ---------------------------------------------------------------------------
// Kernel 2: means = sums / (count + (count==0))
// ---------------------------------------------------------------------------
__global__ void means_kernel(float* __restrict__ out_means) {
    int i = blockIdx.x * blockDim.x + threadIdx.x;  // 0..4095
    if (i >= K_DIM * C_DIM) return;
    int k = i >> 6;
    float cnt = g_counts[k];
    float denom = cnt + (cnt == 0.0f ? 1.0f : 0.0f);
    out_means[i] = g_sums[i] / denom;
}

// ---------------------------------------------------------------------------
// Kernel 3: input_r = broadcast x K_DIM times. The 1 GiB write that dominates.
// 2D grid: y = replica index k, x covers the 16 MB image in float4 strides.
// x stays L2-resident across replicas -> DRAM traffic ~= pure write stream.
// ---------------------------------------------------------------------------
__global__ __launch_bounds__(256) void broadcast_kernel(
    const float4* __restrict__ x4, float4* __restrict__ out4)
{
    const int N4 = (C_DIM * P_DIM) / 4;            // 1,048,576 float4 per replica
    int k = blockIdx.y;
    float4* dst = out4 + (size_t)k * N4;
    int stride = gridDim.x * blockDim.x;
    for (int j = blockIdx.x * blockDim.x + threadIdx.x; j < N4; j += stride) {
        dst[j] = __ldg(&x4[j]);
    }
}

// ---------------------------------------------------------------------------
extern "C" void kernel_launch(void* const* d_in, const int* in_sizes, int n_in,
                              void* d_out, int out_size)
{
    const float* x  = (const float*)d_in[0];       // [1, 64, 256, 256]
    const float* oh = (const float*)d_in[1];       // [1, 64, 256, 256] one-hot
    float* out = (float*)d_out;

    // Output layout: input_r (K*C*H*W floats) followed by regional_means (K*C).
    float* out_means = out + (size_t)out_size - (size_t)(K_DIM * C_DIM);

    zero_kernel<<<1, 256>>>();
    region_sums_kernel<<<P_DIM / 256, 256>>>(x, oh);
    means_kernel<<<(K_DIM * C_DIM + 255) / 256, 256>>>(out_means);

    dim3 grid(1024, K_DIM, 1);
    broadcast_kernel<<<grid, 256>>>((const float4*)x, (float4*)out);
}

// round 2
// speedup vs baseline: 1.1751x; 1.1751x over previous
#include <cuda_runtime.h>
#include <cstddef>

#define C_DIM 64
#define K_DIM 64
#define P_DIM (256 * 256)        // H*W = 65536
#define RED_BLOCKS 256           // reduction blocks (256 pixels each)
#define N4_PER_REP (C_DIM * P_DIM / 4)   // 1,048,576 float4 per replica
#define CHUNKS_PER_REP 1024      // broadcast chunks per replica
#define F4_PER_CHUNK (N4_PER_REP / CHUNKS_PER_REP)  // 1024 float4 = 16KB

// Per-block partial sums — written unconditionally, so no zeroing needed.
__device__ float g_partial[RED_BLOCKS][K_DIM * C_DIM];   // 4 MB
__device__ float g_pcnt[RED_BLOCKS][K_DIM];              // 64 KB

// ---------------------------------------------------------------------------
// Fused kernel: blocks [0, RED_BLOCKS) compute per-region partial sums;
// blocks [RED_BLOCKS, RED_BLOCKS + 65536) stream the 1 GiB broadcast copy.
// The reduction (ATOMS/issue-bound) hides entirely under the DRAM-bound copy.
// ---------------------------------------------------------------------------
__global__ __launch_bounds__(256) void fused_kernel(
    const float* __restrict__ x, const float* __restrict__ oh,
    float4* __restrict__ out4)
{
    __shared__ float ssum[K_DIM][C_DIM + 1];  // padded rows vs bank conflicts
    __shared__ float scnt[K_DIM];

    int bid = blockIdx.x;
    int tid = threadIdx.x;

    if (bid < RED_BLOCKS) {
        // ---- reduction path: 256 pixels per block ----
        for (int i = tid; i < K_DIM * (C_DIM + 1); i += 256)
            (&ssum[0][0])[i] = 0.0f;
        if (tid < K_DIM) scnt[tid] = 0.0f;
        __syncthreads();

        int p = bid * 256 + tid;

        // Recover the one-hot label (coalesced scan over K).
        int label = 0;
        #pragma unroll 8
        for (int k = 0; k < K_DIM; k++) {
            if (__ldg(&oh[(size_t)k * P_DIM + p]) != 0.0f) label = k;
        }
        atomicAdd(&scnt[label], 1.0f);

        #pragma unroll 8
        for (int c = 0; c < C_DIM; c++) {
            atomicAdd(&ssum[label][c], __ldg(&x[(size_t)c * P_DIM + p]));
        }
        __syncthreads();

        // Non-atomic flush to this block's private partial slot.
        for (int i = tid; i < K_DIM * C_DIM; i += 256) {
            g_partial[bid][i] = ssum[i >> 6][i & 63];
        }
        if (tid < K_DIM) g_pcnt[bid][tid] = scnt[tid];
    } else {
        // ---- broadcast path: one 16 KB chunk of one replica ----
        int b  = bid - RED_BLOCKS;
        int k  = b >> 10;              // replica index
        int cb = b & (CHUNKS_PER_REP - 1);

        const float4* src = (const float4*)x + (size_t)cb * F4_PER_CHUNK;
        float4* dst = out4 + (size_t)k * N4_PER_REP + (size_t)cb * F4_PER_CHUNK;

        // 1024 float4 per chunk, 256 threads -> 4 each; batch loads for MLP.
        float4 v0 = __ldg(src + tid);
        float4 v1 = __ldg(src + 256 + tid);
        float4 v2 = __ldg(src + 512 + tid);
        float4 v3 = __ldg(src + 768 + tid);
        __stcs(dst + tid,       v0);
        __stcs(dst + 256 + tid, v1);
        __stcs(dst + 512 + tid, v2);
        __stcs(dst + 768 + tid, v3);
    }
}

// ---------------------------------------------------------------------------
// Final means: reduce the 256 partials per (k,c) and divide by counts.
// 16 blocks x 256 threads = 4096 threads, one per (k,c).
// ---------------------------------------------------------------------------
__global__ __launch_bounds__(256) void means_kernel(float* __restrict__ out_means)
{
    __shared__ float sdenom[4];   // 4 k-values per block (256 entries / 64 c)

    int i = blockIdx.x * 256 + threadIdx.x;   // (k,c) flat index

    if (threadIdx.x < 4) {
        int kk = blockIdx.x * 4 + threadIdx.x;
        float cnt = 0.0f;
        #pragma unroll 8
        for (int r = 0; r < RED_BLOCKS; r++) cnt += g_pcnt[r][kk];
        sdenom[threadIdx.x] = cnt + (cnt == 0.0f ? 1.0f : 0.0f);
    }
    __syncthreads();

    float s = 0.0f;
    #pragma unroll 8
    for (int r = 0; r < RED_BLOCKS; r++) s += g_partial[r][i];

    out_means[i] = s / sdenom[threadIdx.x >> 6];
}

// ---------------------------------------------------------------------------
extern "C" void kernel_launch(void* const* d_in, const int* in_sizes, int n_in,
                              void* d_out, int out_size)
{
    const float* x  = (const float*)d_in[0];   // [1, 64, 256, 256]
    const float* oh = (const float*)d_in[1];   // [1, 64, 256, 256] one-hot
    float* out = (float*)d_out;

    // Output layout: input_r (K*C*H*W floats) then regional_means (K*C).
    float* out_means = out + (size_t)out_size - (size_t)(K_DIM * C_DIM);

    fused_kernel<<<RED_BLOCKS + K_DIM * CHUNKS_PER_REP, 256>>>(
        x, oh, (float4*)out);
    means_kernel<<<(K_DIM * C_DIM) / 256, 256>>>(out_means);
}